// round 1
// baseline (speedup 1.0000x reference)
#include <cuda_runtime.h>

#define NN 100000
#define EE 1600000
#define FIN 100
#define HID 128
#define NC 47
#define NC_PAD 48

// ---- scratch (device globals; no runtime allocation allowed) ----
__device__ float g_dinv[NN];                    // deg, then rsqrt(deg)
__device__ float g_aggx[NN * FIN];              // aggregated input features (A~ X)
__device__ float g_h[NN * HID];                 // relu((A~X)W1 + b1)
__device__ float g_hw[NN * NC_PAD];             // h @ W2 (padded to 48 cols, pad=0)
__device__ float g_outp[NN * NC_PAD];           // aggregated output (padded)

__device__ __forceinline__ void red_add_f32x4(float* addr, float4 v) {
    asm volatile("red.global.add.v4.f32 [%0], {%1,%2,%3,%4};"
                 :: "l"(addr), "f"(v.x), "f"(v.y), "f"(v.z), "f"(v.w)
                 : "memory");
}

// ---------------- degree / norm ----------------
__global__ void k_init_deg() {
    int i = blockIdx.x * blockDim.x + threadIdx.x;
    if (i < NN) g_dinv[i] = 1.0f;                // self loop
}

__global__ void k_count_deg(const int* __restrict__ ei) {
    int e = blockIdx.x * blockDim.x + threadIdx.x;
    if (e < EE) atomicAdd(&g_dinv[ei[EE + e]], 1.0f);
}

__global__ void k_rsqrt() {
    int i = blockIdx.x * blockDim.x + threadIdx.x;
    if (i < NN) g_dinv[i] = rsqrtf(g_dinv[i]);   // deg >= 1 always
}

// ---------------- layer 1: aggregate x (self loops) ----------------
__global__ void k_init_aggx(const float* __restrict__ x) {
    int i = blockIdx.x * blockDim.x + threadIdx.x;   // over NN*25 float4s
    if (i >= NN * (FIN / 4)) return;
    int row = i / (FIN / 4);
    float s = g_dinv[row]; s *= s;
    float4 v = ((const float4*)x)[i];
    v.x *= s; v.y *= s; v.z *= s; v.w *= s;
    ((float4*)g_aggx)[i] = v;
}

// one warp per edge; lanes 0..24 move 25 float4s (100 floats)
__global__ void k_edge1(const int* __restrict__ ei, const float* __restrict__ x) {
    int t = blockIdx.x * blockDim.x + threadIdx.x;
    int e = t >> 5, lane = t & 31;
    if (e >= EE) return;
    int s = ei[e];
    int d = ei[EE + e];
    float nrm = g_dinv[s] * g_dinv[d];
    if (lane < FIN / 4) {
        float4 v = ((const float4*)x)[s * (FIN / 4) + lane];
        v.x *= nrm; v.y *= nrm; v.z *= nrm; v.w *= nrm;
        red_add_f32x4((float*)(((float4*)g_aggx) + d * (FIN / 4) + lane), v);
    }
}

// ---------------- GEMM1: g_h = relu(g_aggx @ W1 + b1), M=NN K=100 N=128 ----------------
// 64 rows x 128 cols per block, 128 threads, 8x8 per thread, K in 2 chunks of 50.
__global__ void k_gemm1(const float* __restrict__ W1, const float* __restrict__ b1) {
    __shared__ float As[50 * 68];     // [k][m], padded stride 68
    __shared__ float Bs[50 * 128];    // [k][j]
    int tid = threadIdx.x;
    int row0 = blockIdx.x * 64;
    int ty = tid >> 4, tx = tid & 15;
    float acc[8][8];
#pragma unroll
    for (int r = 0; r < 8; r++)
#pragma unroll
        for (int c = 0; c < 8; c++) acc[r][c] = 0.f;

    for (int kc = 0; kc < FIN; kc += 50) {
        __syncthreads();
        for (int i = tid; i < 64 * 50; i += 128) {
            int m = i / 50, k = i - m * 50;
            int gr = row0 + m;
            As[k * 68 + m] = (gr < NN) ? g_aggx[gr * FIN + kc + k] : 0.f;
        }
        for (int i = tid; i < 50 * 128; i += 128)
            Bs[i] = W1[kc * 128 + i];
        __syncthreads();
#pragma unroll 2
        for (int k = 0; k < 50; k++) {
            float4 a0 = *(const float4*)&As[k * 68 + ty * 8];
            float4 a1 = *(const float4*)&As[k * 68 + ty * 8 + 4];
            float4 b0 = *(const float4*)&Bs[k * 128 + tx * 8];
            float4 b1v = *(const float4*)&Bs[k * 128 + tx * 8 + 4];
            float av[8] = {a0.x, a0.y, a0.z, a0.w, a1.x, a1.y, a1.z, a1.w};
            float bv[8] = {b0.x, b0.y, b0.z, b0.w, b1v.x, b1v.y, b1v.z, b1v.w};
#pragma unroll
            for (int r = 0; r < 8; r++)
#pragma unroll
                for (int c = 0; c < 8; c++)
                    acc[r][c] += av[r] * bv[c];
        }
    }
    int cb = tx * 8;
    float4 bb0 = *(const float4*)&b1[cb];
    float4 bb1 = *(const float4*)&b1[cb + 4];
    float bb[8] = {bb0.x, bb0.y, bb0.z, bb0.w, bb1.x, bb1.y, bb1.z, bb1.w};
#pragma unroll
    for (int r = 0; r < 8; r++) {
        int row = row0 + ty * 8 + r;
        if (row < NN) {
#pragma unroll
            for (int c = 0; c < 8; c++) {
                float v = acc[r][c] + bb[c];
                g_h[row * HID + cb + c] = v > 0.f ? v : 0.f;
            }
        }
    }
}

// ---------------- GEMM2: g_hw = g_h @ W2 (pad to 48); also init g_outp = g_hw*dinv^2 ----------------
// 64 rows x 48 cols per block, 128 threads, 8x3 per thread, K=128 in 2 chunks of 64.
__global__ void k_gemm2(const float* __restrict__ W2) {
    __shared__ float As[64 * 68];       // [k][m], stride 68
    __shared__ float Bs[64 * NC_PAD];   // [k][j], col 47 zero-padded
    int tid = threadIdx.x;
    int row0 = blockIdx.x * 64;
    int ty = tid >> 4, tx = tid & 15;   // 8 rows x 3 cols per thread
    float acc[8][3];
#pragma unroll
    for (int r = 0; r < 8; r++)
#pragma unroll
        for (int c = 0; c < 3; c++) acc[r][c] = 0.f;

    for (int kc = 0; kc < HID; kc += 64) {
        __syncthreads();
        for (int i = tid; i < 64 * 64; i += 128) {
            int m = i >> 6, k = i & 63;
            int gr = row0 + m;
            As[k * 68 + m] = (gr < NN) ? g_h[gr * HID + kc + k] : 0.f;
        }
        for (int i = tid; i < 64 * NC_PAD; i += 128) {
            int k = i / NC_PAD, j = i - k * NC_PAD;
            Bs[i] = (j < NC) ? W2[(kc + k) * NC + j] : 0.f;
        }
        __syncthreads();
#pragma unroll 4
        for (int k = 0; k < 64; k++) {
            float4 a0 = *(const float4*)&As[k * 68 + ty * 8];
            float4 a1 = *(const float4*)&As[k * 68 + ty * 8 + 4];
            float b0 = Bs[k * NC_PAD + tx * 3];
            float b1v = Bs[k * NC_PAD + tx * 3 + 1];
            float b2v = Bs[k * NC_PAD + tx * 3 + 2];
            float av[8] = {a0.x, a0.y, a0.z, a0.w, a1.x, a1.y, a1.z, a1.w};
#pragma unroll
            for (int r = 0; r < 8; r++) {
                acc[r][0] += av[r] * b0;
                acc[r][1] += av[r] * b1v;
                acc[r][2] += av[r] * b2v;
            }
        }
    }
#pragma unroll
    for (int r = 0; r < 8; r++) {
        int row = row0 + ty * 8 + r;
        if (row < NN) {
            float di = g_dinv[row];
            float d2 = di * di;
#pragma unroll
            for (int c = 0; c < 3; c++) {
                int col = tx * 3 + c;
                float v = acc[r][c];
                g_hw[row * NC_PAD + col] = v;
                g_outp[row * NC_PAD + col] = v * d2;   // self-loop contribution
            }
        }
    }
}

// half-warp per edge; sublanes 0..11 move 12 float4s (48 floats, col 47 is zero pad)
__global__ void k_edge2(const int* __restrict__ ei) {
    int t = blockIdx.x * blockDim.x + threadIdx.x;
    int e = t >> 4, lane = t & 15;
    if (e >= EE || lane >= NC_PAD / 4) return;
    int s = ei[e];
    int d = ei[EE + e];
    float nrm = g_dinv[s] * g_dinv[d];
    float4 v = ((const float4*)g_hw)[s * (NC_PAD / 4) + lane];
    v.x *= nrm; v.y *= nrm; v.z *= nrm; v.w *= nrm;
    red_add_f32x4((float*)(((float4*)g_outp) + d * (NC_PAD / 4) + lane), v);
}

// strip the pad column, add b2
__global__ void k_final(const float* __restrict__ b2, float* __restrict__ out) {
    int i = blockIdx.x * blockDim.x + threadIdx.x;
    if (i >= NN * NC) return;
    int row = i / NC, c = i - row * NC;
    out[i] = g_outp[row * NC_PAD + c] + b2[c];
}

extern "C" void kernel_launch(void* const* d_in, const int* in_sizes, int n_in,
                              void* d_out, int out_size) {
    const float* x  = (const float*)d_in[0];
    const int*   ei = (const int*)d_in[1];
    const float* W1 = (const float*)d_in[2];
    const float* b1 = (const float*)d_in[3];
    const float* W2 = (const float*)d_in[4];
    const float* b2 = (const float*)d_in[5];
    float* out = (float*)d_out;

    // degree / normalization
    k_init_deg<<<(NN + 255) / 256, 256>>>();
    k_count_deg<<<(EE + 255) / 256, 256>>>(ei);
    k_rsqrt<<<(NN + 255) / 256, 256>>>();

    // layer 1: aggregate raw features (A~ X), then GEMM+bias+relu
    k_init_aggx<<<(NN * (FIN / 4) + 255) / 256, 256>>>(x);
    {
        long long threads = (long long)EE * 32;
        int blocks = (int)((threads + 255) / 256);
        k_edge1<<<blocks, 256>>>(ei, x);
    }
    k_gemm1<<<(NN + 63) / 64, 128>>>(W1, b1);

    // layer 2: GEMM first (47 wide), then aggregate
    k_gemm2<<<(NN + 63) / 64, 128>>>(W2);
    {
        long long threads = (long long)EE * 16;
        int blocks = (int)((threads + 255) / 256);
        k_edge2<<<blocks, 256>>>(ei);
    }
    k_final<<<(NN * NC + 255) / 256, 256>>>(b2, out);
}

// round 2
// speedup vs baseline: 1.9868x; 1.9868x over previous
#include <cuda_runtime.h>

#define NN 100000
#define NN_PAD 102400     // padded for int4 scan loads (25 chunks of 4096)
#define EE 1600000
#define FIN 100
#define HID 128
#define NC 47
#define NC_PAD 48

// ---- scratch (device globals; no runtime allocation allowed) ----
__device__ int   g_degi[NN_PAD];      // in-degree counts (no self loop)
__device__ int   g_rowstart[NN];      // CSR row offsets
__device__ int   g_eord[EE];          // per-edge ordinal within its dst bucket
__device__ int   g_csr[EE];           // source node ids, bucketed by dst
__device__ float g_dinv[NN];          // rsqrt(deg+1)
__device__ float g_aggx[NN * FIN];    // A~ X
__device__ float g_h[NN * HID];       // relu((A~X)W1 + b1)
__device__ float g_hw[NN * NC_PAD];   // h @ W2 (col 47 zero pad)

// ---------------- CSR build ----------------
__global__ void k_zero() {
    int i = blockIdx.x * blockDim.x + threadIdx.x;
    if (i < NN_PAD) g_degi[i] = 0;
}

__global__ void k_deg(const int* __restrict__ ei) {
    int e = blockIdx.x * blockDim.x + threadIdx.x;
    if (e < EE) g_eord[e] = atomicAdd(&g_degi[ei[EE + e]], 1);
}

// single-block exclusive prefix sum over NN_PAD ints (4096 per chunk, 25 chunks)
__global__ void k_scan() {
    __shared__ int sh_w[32];
    __shared__ int sh_tot;
    int tid = threadIdx.x;
    int lane = tid & 31, wid = tid >> 5;
    int carry = 0;
    for (int base = 0; base < NN_PAD; base += 4096) {
        int i0 = base + tid * 4;
        int4 d = ((const int4*)g_degi)[i0 >> 2];
        int s0 = d.x, s1 = s0 + d.y, s2 = s1 + d.z, s3 = s2 + d.w;
        int tsum = s3;
        // warp inclusive scan of tsum
        int v = tsum;
        #pragma unroll
        for (int off = 1; off < 32; off <<= 1) {
            int t = __shfl_up_sync(0xffffffffu, v, off);
            if (lane >= off) v += t;
        }
        int wexcl = v - tsum;
        if (lane == 31) sh_w[wid] = v;
        __syncthreads();
        if (wid == 0) {
            int wv = sh_w[lane];
            int u = wv;
            #pragma unroll
            for (int off = 1; off < 32; off <<= 1) {
                int t = __shfl_up_sync(0xffffffffu, u, off);
                if (lane >= off) u += t;
            }
            sh_w[lane] = u - wv;
            if (lane == 31) sh_tot = u;
        }
        __syncthreads();
        int off0 = carry + sh_w[wid] + wexcl;
        if (i0 + 0 < NN) g_rowstart[i0 + 0] = off0;
        if (i0 + 1 < NN) g_rowstart[i0 + 1] = off0 + s0;
        if (i0 + 2 < NN) g_rowstart[i0 + 2] = off0 + s1;
        if (i0 + 3 < NN) g_rowstart[i0 + 3] = off0 + s2;
        carry += sh_tot;
        __syncthreads();
    }
}

__global__ void k_dinv() {
    int i = blockIdx.x * blockDim.x + threadIdx.x;
    if (i < NN) g_dinv[i] = rsqrtf((float)g_degi[i] + 1.0f);
}

__global__ void k_fill(const int* __restrict__ ei) {
    int e = blockIdx.x * blockDim.x + threadIdx.x;
    if (e < EE) g_csr[g_rowstart[ei[EE + e]] + g_eord[e]] = ei[e];
}

// ---------------- layer 1 aggregation: warp per node, gather-only ----------------
// agg[d] = dinv[d] * ( dinv[d]*x[d] + sum_s dinv[s]*x[s] )
__global__ void k_agg1(const float* __restrict__ x) {
    int t = blockIdx.x * blockDim.x + threadIdx.x;
    int node = t >> 5, lane = t & 31;
    if (node >= NN) return;
    bool act = lane < FIN / 4;
    const float4* x4 = (const float4*)x;
    float wd = g_dinv[node];
    float4 acc = make_float4(0.f, 0.f, 0.f, 0.f);
    if (act) {
        float4 v = x4[node * (FIN / 4) + lane];
        acc.x = wd * v.x; acc.y = wd * v.y; acc.z = wd * v.z; acc.w = wd * v.w;
    }
    int start = g_rowstart[node];
    int end = start + g_degi[node];
    int j = start;
    for (; j + 1 < end; j += 2) {
        int s0 = g_csr[j], s1 = g_csr[j + 1];
        float w0 = g_dinv[s0], w1 = g_dinv[s1];
        if (act) {
            float4 v0 = x4[s0 * (FIN / 4) + lane];
            float4 v1 = x4[s1 * (FIN / 4) + lane];
            acc.x += w0 * v0.x + w1 * v1.x;
            acc.y += w0 * v0.y + w1 * v1.y;
            acc.z += w0 * v0.z + w1 * v1.z;
            acc.w += w0 * v0.w + w1 * v1.w;
        }
    }
    if (j < end) {
        int s0 = g_csr[j];
        float w0 = g_dinv[s0];
        if (act) {
            float4 v0 = x4[s0 * (FIN / 4) + lane];
            acc.x += w0 * v0.x; acc.y += w0 * v0.y;
            acc.z += w0 * v0.z; acc.w += w0 * v0.w;
        }
    }
    if (act) {
        acc.x *= wd; acc.y *= wd; acc.z *= wd; acc.w *= wd;
        ((float4*)g_aggx)[node * (FIN / 4) + lane] = acc;
    }
}

// ---------------- GEMM1: g_h = relu(g_aggx @ W1 + b1), M=NN K=100 N=128 ----------------
__global__ void k_gemm1(const float* __restrict__ W1, const float* __restrict__ b1) {
    __shared__ float As[50 * 68];
    __shared__ float Bs[50 * 128];
    int tid = threadIdx.x;
    int row0 = blockIdx.x * 64;
    int ty = tid >> 4, tx = tid & 15;
    float acc[8][8];
#pragma unroll
    for (int r = 0; r < 8; r++)
#pragma unroll
        for (int c = 0; c < 8; c++) acc[r][c] = 0.f;

    for (int kc = 0; kc < FIN; kc += 50) {
        __syncthreads();
        for (int i = tid; i < 64 * 50; i += 128) {
            int m = i / 50, k = i - m * 50;
            int gr = row0 + m;
            As[k * 68 + m] = (gr < NN) ? g_aggx[gr * FIN + kc + k] : 0.f;
        }
        for (int i = tid; i < 50 * 128; i += 128)
            Bs[i] = W1[kc * 128 + i];
        __syncthreads();
#pragma unroll 2
        for (int k = 0; k < 50; k++) {
            float4 a0 = *(const float4*)&As[k * 68 + ty * 8];
            float4 a1 = *(const float4*)&As[k * 68 + ty * 8 + 4];
            float4 b0 = *(const float4*)&Bs[k * 128 + tx * 8];
            float4 b1v = *(const float4*)&Bs[k * 128 + tx * 8 + 4];
            float av[8] = {a0.x, a0.y, a0.z, a0.w, a1.x, a1.y, a1.z, a1.w};
            float bv[8] = {b0.x, b0.y, b0.z, b0.w, b1v.x, b1v.y, b1v.z, b1v.w};
#pragma unroll
            for (int r = 0; r < 8; r++)
#pragma unroll
                for (int c = 0; c < 8; c++)
                    acc[r][c] += av[r] * bv[c];
        }
    }
    int cb = tx * 8;
    float4 bb0 = *(const float4*)&b1[cb];
    float4 bb1 = *(const float4*)&b1[cb + 4];
    float bb[8] = {bb0.x, bb0.y, bb0.z, bb0.w, bb1.x, bb1.y, bb1.z, bb1.w};
#pragma unroll
    for (int r = 0; r < 8; r++) {
        int row = row0 + ty * 8 + r;
        if (row < NN) {
#pragma unroll
            for (int c = 0; c < 8; c++) {
                float v = acc[r][c] + bb[c];
                g_h[row * HID + cb + c] = v > 0.f ? v : 0.f;
            }
        }
    }
}

// ---------------- GEMM2: g_hw = g_h @ W2 (padded to 48 cols) ----------------
__global__ void k_gemm2(const float* __restrict__ W2) {
    __shared__ float As[64 * 68];
    __shared__ float Bs[64 * NC_PAD];
    int tid = threadIdx.x;
    int row0 = blockIdx.x * 64;
    int ty = tid >> 4, tx = tid & 15;
    float acc[8][3];
#pragma unroll
    for (int r = 0; r < 8; r++)
#pragma unroll
        for (int c = 0; c < 3; c++) acc[r][c] = 0.f;

    for (int kc = 0; kc < HID; kc += 64) {
        __syncthreads();
        for (int i = tid; i < 64 * 64; i += 128) {
            int m = i >> 6, k = i & 63;
            int gr = row0 + m;
            As[k * 68 + m] = (gr < NN) ? g_h[gr * HID + kc + k] : 0.f;
        }
        for (int i = tid; i < 64 * NC_PAD; i += 128) {
            int k = i / NC_PAD, j = i - k * NC_PAD;
            Bs[i] = (j < NC) ? W2[(kc + k) * NC + j] : 0.f;
        }
        __syncthreads();
#pragma unroll 4
        for (int k = 0; k < 64; k++) {
            float4 a0 = *(const float4*)&As[k * 68 + ty * 8];
            float4 a1 = *(const float4*)&As[k * 68 + ty * 8 + 4];
            float b0 = Bs[k * NC_PAD + tx * 3];
            float b1v = Bs[k * NC_PAD + tx * 3 + 1];
            float b2v = Bs[k * NC_PAD + tx * 3 + 2];
            float av[8] = {a0.x, a0.y, a0.z, a0.w, a1.x, a1.y, a1.z, a1.w};
#pragma unroll
            for (int r = 0; r < 8; r++) {
                acc[r][0] += av[r] * b0;
                acc[r][1] += av[r] * b1v;
                acc[r][2] += av[r] * b2v;
            }
        }
    }
#pragma unroll
    for (int r = 0; r < 8; r++) {
        int row = row0 + ty * 8 + r;
        if (row < NN) {
#pragma unroll
            for (int c = 0; c < 3; c++)
                g_hw[row * NC_PAD + tx * 3 + c] = acc[r][c];
        }
    }
}

// ---------------- layer 2 aggregation: half-warp per node, fused bias + pad-strip ----------------
__global__ void k_agg2(const float* __restrict__ b2, float* __restrict__ out) {
    int t = blockIdx.x * blockDim.x + threadIdx.x;
    int node = t >> 4, sub = t & 15;
    if (node >= NN) return;
    bool act = sub < NC_PAD / 4;
    const float4* hw4 = (const float4*)g_hw;
    float wd = g_dinv[node];
    float4 acc = make_float4(0.f, 0.f, 0.f, 0.f);
    if (act) {
        float4 v = hw4[node * (NC_PAD / 4) + sub];
        acc.x = wd * v.x; acc.y = wd * v.y; acc.z = wd * v.z; acc.w = wd * v.w;
    }
    int start = g_rowstart[node];
    int end = start + g_degi[node];
    int j = start;
    for (; j + 1 < end; j += 2) {
        int s0 = g_csr[j], s1 = g_csr[j + 1];
        float w0 = g_dinv[s0], w1 = g_dinv[s1];
        if (act) {
            float4 v0 = hw4[s0 * (NC_PAD / 4) + sub];
            float4 v1 = hw4[s1 * (NC_PAD / 4) + sub];
            acc.x += w0 * v0.x + w1 * v1.x;
            acc.y += w0 * v0.y + w1 * v1.y;
            acc.z += w0 * v0.z + w1 * v1.z;
            acc.w += w0 * v0.w + w1 * v1.w;
        }
    }
    if (j < end) {
        int s0 = g_csr[j];
        float w0 = g_dinv[s0];
        if (act) {
            float4 v0 = hw4[s0 * (NC_PAD / 4) + sub];
            acc.x += w0 * v0.x; acc.y += w0 * v0.y;
            acc.z += w0 * v0.z; acc.w += w0 * v0.w;
        }
    }
    if (act) {
        float vv[4] = {acc.x * wd, acc.y * wd, acc.z * wd, acc.w * wd};
        int cb = sub * 4;
#pragma unroll
        for (int k = 0; k < 4; k++) {
            int c = cb + k;
            if (c < NC) out[node * NC + c] = vv[k] + b2[c];
        }
    }
}

extern "C" void kernel_launch(void* const* d_in, const int* in_sizes, int n_in,
                              void* d_out, int out_size) {
    const float* x  = (const float*)d_in[0];
    const int*   ei = (const int*)d_in[1];
    const float* W1 = (const float*)d_in[2];
    const float* b1 = (const float*)d_in[3];
    const float* W2 = (const float*)d_in[4];
    const float* b2 = (const float*)d_in[5];
    float* out = (float*)d_out;

    // CSR build + normalization
    k_zero<<<(NN_PAD + 255) / 256, 256>>>();
    k_deg<<<(EE + 255) / 256, 256>>>(ei);
    k_scan<<<1, 1024>>>();
    k_dinv<<<(NN + 255) / 256, 256>>>();
    k_fill<<<(EE + 255) / 256, 256>>>(ei);

    // layer 1: gather-aggregate raw features, then GEMM+bias+relu
    k_agg1<<<(NN * 32 + 255) / 256, 256>>>(x);
    k_gemm1<<<(NN + 63) / 64, 128>>>(W1, b1);

    // layer 2: GEMM first (47 wide), then gather-aggregate with fused epilogue
    k_gemm2<<<(NN + 63) / 64, 128>>>(W2);
    k_agg2<<<(NN * 16 + 255) / 256, 256>>>(b2, out);
}